// round 1
// baseline (speedup 1.0000x reference)
#include <cuda_runtime.h>
#include <cstdint>

#define N_NODES 1048576
#define N_SEGS  8192
#define D_IN    128
#define D_H     64
#define TM      128            // nodes per tile

// ---------------- scratch (static device global: no allocs allowed) ----------
__device__ float g_tokens[N_SEGS * D_H];

// ---------------- smem layout (floats) for main kernel ----------------------
#define XS_STRIDE 132          // 128 + 4 pad -> (4r+c)%32 conflict-free frags
#define W1_STRIDE 132
#define W2_STRIDE 68
#define HS_STRIDE 68
#define X_TILE_F  (TM * XS_STRIDE)                 // 16896
#define OFF_X0    0
#define OFF_X1    (X_TILE_F)
#define OFF_W1    (2 * X_TILE_F)                   // 33792
#define OFF_W2    (OFF_W1 + 64 * W1_STRIDE)        // +8448
#define OFF_H     (OFF_W2 + 64 * W2_STRIDE)        // +4352
#define OFF_B1    (OFF_H + TM * HS_STRIDE)         // +8704
#define OFF_B2    (OFF_B1 + 64)
#define OFF_SEG   (OFF_B2 + 64)                    // 128 ints
#define SMEM_MAIN_FLOATS (OFF_SEG + TM)
#define SMEM_MAIN_BYTES  (SMEM_MAIN_FLOATS * 4)    // 222208 B

// ---------------- helpers ----------------------------------------------------
__device__ __forceinline__ uint32_t f2tf32(float f) {
    uint32_t r;
    asm volatile("cvt.rna.tf32.f32 %0, %1;\n" : "=r"(r) : "f"(f));
    return r;
}
__device__ __forceinline__ float tf32r(float f) { return __uint_as_float(f2tf32(f)); }

__device__ __forceinline__ void mma_tf32(float c[4],
                                         uint32_t a0, uint32_t a1, uint32_t a2, uint32_t a3,
                                         uint32_t b0, uint32_t b1) {
    asm volatile(
        "mma.sync.aligned.m16n8k8.row.col.f32.tf32.tf32.f32 "
        "{%0,%1,%2,%3}, {%4,%5,%6,%7}, {%8,%9}, {%0,%1,%2,%3};\n"
        : "+f"(c[0]), "+f"(c[1]), "+f"(c[2]), "+f"(c[3])
        : "r"(a0), "r"(a1), "r"(a2), "r"(a3), "r"(b0), "r"(b1));
}

__device__ __forceinline__ void cp_async16(float* dst, const float* src) {
    uint32_t d = (uint32_t)__cvta_generic_to_shared(dst);
    asm volatile("cp.async.cg.shared.global [%0], [%1], 16;\n" :: "r"(d), "l"(src));
}

__device__ __forceinline__ void load_tile_async(float* dst, const float* __restrict__ x,
                                                int tile, int tid) {
    const float* src = x + (size_t)tile * TM * D_IN;
    #pragma unroll
    for (int i = 0; i < 16; i++) {
        int cid = tid + i * 256;          // 4096 16B chunks total
        int r   = cid >> 5;               // 32 chunks per row
        int c4  = cid & 31;
        cp_async16(dst + r * XS_STRIDE + c4 * 4, src + r * D_IN + c4 * 4);
    }
}

// ---------------- kernel 1: zero tokens --------------------------------------
__global__ void zero_tokens_kernel() {
    int i = blockIdx.x * blockDim.x + threadIdx.x;
    if (i < N_SEGS * D_H) g_tokens[i] = 0.0f;
}

// ---------------- kernel 2: fused MLP (2 GEMMs) + segment sum ----------------
__global__ void __launch_bounds__(256, 1)
mlp_seg_kernel(const float* __restrict__ x, const int* __restrict__ offset,
               const float* __restrict__ W1, const float* __restrict__ b1,
               const float* __restrict__ W2, const float* __restrict__ b2) {
    extern __shared__ float sm[];
    const int tid = threadIdx.x;

    // Stage weights once per block (rounded to tf32 so MMA truncation is unbiased)
    for (int i = tid; i < 64 * 128; i += 256) {
        int r = i >> 7, c = i & 127;
        sm[OFF_W1 + r * W1_STRIDE + c] = tf32r(W1[i]);
    }
    for (int i = tid; i < 64 * 64; i += 256) {
        int r = i >> 6, c = i & 63;
        sm[OFF_W2 + r * W2_STRIDE + c] = tf32r(W2[i]);
    }
    if (tid < 64) { sm[OFF_B1 + tid] = b1[tid]; sm[OFF_B2 + tid] = b2[tid]; }

    const int lane = tid & 31, warp = tid >> 5;
    const int gid = lane >> 2, tig = lane & 3;      // groupID / threadInGroup
    const int rm = (warp >> 1) * 32;                // warp M-tile base (4 warps)
    const int cn = (warp & 1) * 32;                 // warp N-tile base (2 warps)

    const int nTiles = N_NODES / TM;                // 8192
    int* segsm = (int*)(sm + OFF_SEG);

    // Prefetch the first tile before the weight-stage sync (independent)
    if ((int)blockIdx.x < nTiles)
        load_tile_async(sm + OFF_X0, x, blockIdx.x, tid);
    asm volatile("cp.async.commit_group;\n");
    __syncthreads();   // weights ready

    int cur = 0;
    for (int t = blockIdx.x; t < nTiles; t += gridDim.x) {
        // prefetch next tile into the other buffer; always commit (empty ok)
        int tn = t + gridDim.x;
        if (tn < nTiles)
            load_tile_async(sm + (cur ? OFF_X0 : OFF_X1), x, tn, tid);
        asm volatile("cp.async.commit_group;\n");
        asm volatile("cp.async.wait_group 1;\n");   // wait for current tile's group

        float* Xs = sm + (cur ? OFF_X1 : OFF_X0);

        // Round current X tile to tf32 in place (each thread rounds exactly the
        // chunks it copied -> no sync needed before this)
        #pragma unroll 4
        for (int i = tid; i < TM * 32; i += 256) {
            int r = i >> 5, c4 = i & 31;
            float4* p = (float4*)(Xs + r * XS_STRIDE + c4 * 4);
            float4 v = *p;
            v.x = tf32r(v.x); v.y = tf32r(v.y); v.z = tf32r(v.z); v.w = tf32r(v.w);
            *p = v;
        }

        // Per-row segment ids (upper_bound(offset, node) - 1); offset cached in L1/L2
        if (tid < TM) {
            int node = t * TM + tid;
            int lo = 0, hi = N_SEGS;
            #pragma unroll 1
            while (hi - lo > 1) {
                int mid = (lo + hi) >> 1;
                if (offset[mid] <= node) lo = mid; else hi = mid;
            }
            segsm[tid] = lo;
        }
        __syncthreads();   // X rounded + seg ids ready

        // ---------------- GEMM1: H1[128,64] = relu(X[128,128] @ W1^T + b1) ---
        const uint32_t* Xu  = (const uint32_t*)Xs;
        const uint32_t* W1u = (const uint32_t*)(sm + OFF_W1);
        float acc[2][4][4];
        #pragma unroll
        for (int m = 0; m < 2; m++)
            #pragma unroll
            for (int n = 0; n < 4; n++)
                #pragma unroll
                for (int q = 0; q < 4; q++) acc[m][n][q] = 0.0f;

        #pragma unroll
        for (int ks = 0; ks < 16; ks++) {
            int k0 = ks * 8;
            uint32_t bf[4][2];
            #pragma unroll
            for (int n = 0; n < 4; n++) {
                int col = cn + n * 8 + gid;                 // B[k][n] = W1[n][k]
                bf[n][0] = W1u[col * W1_STRIDE + k0 + tig];
                bf[n][1] = W1u[col * W1_STRIDE + k0 + 4 + tig];
            }
            #pragma unroll
            for (int m = 0; m < 2; m++) {
                int r = rm + m * 16 + gid;
                uint32_t a0 = Xu[r * XS_STRIDE + k0 + tig];
                uint32_t a1 = Xu[(r + 8) * XS_STRIDE + k0 + tig];
                uint32_t a2 = Xu[r * XS_STRIDE + k0 + 4 + tig];
                uint32_t a3 = Xu[(r + 8) * XS_STRIDE + k0 + 4 + tig];
                #pragma unroll
                for (int n = 0; n < 4; n++)
                    mma_tf32(acc[m][n], a0, a1, a2, a3, bf[n][0], bf[n][1]);
            }
        }

        // Epilogue 1: bias + relu, write tf32-rounded H1 to smem
        float* Hs = sm + OFF_H;
        #pragma unroll
        for (int m = 0; m < 2; m++) {
            int r = rm + m * 16 + gid;
            #pragma unroll
            for (int n = 0; n < 4; n++) {
                int c = cn + n * 8 + 2 * tig;
                float v0 = fmaxf(acc[m][n][0] + sm[OFF_B1 + c], 0.0f);
                float v1 = fmaxf(acc[m][n][1] + sm[OFF_B1 + c + 1], 0.0f);
                float v2 = fmaxf(acc[m][n][2] + sm[OFF_B1 + c], 0.0f);
                float v3 = fmaxf(acc[m][n][3] + sm[OFF_B1 + c + 1], 0.0f);
                Hs[r * HS_STRIDE + c]           = tf32r(v0);
                Hs[r * HS_STRIDE + c + 1]       = tf32r(v1);
                Hs[(r + 8) * HS_STRIDE + c]     = tf32r(v2);
                Hs[(r + 8) * HS_STRIDE + c + 1] = tf32r(v3);
            }
        }
        __syncthreads();   // H1 visible

        // ---------------- GEMM2: H2[128,64] = relu(H1 @ W2^T + b2) ----------
        const uint32_t* Hu  = (const uint32_t*)Hs;
        const uint32_t* W2u = (const uint32_t*)(sm + OFF_W2);
        float acc2[2][4][4];
        #pragma unroll
        for (int m = 0; m < 2; m++)
            #pragma unroll
            for (int n = 0; n < 4; n++)
                #pragma unroll
                for (int q = 0; q < 4; q++) acc2[m][n][q] = 0.0f;

        #pragma unroll
        for (int ks = 0; ks < 8; ks++) {
            int k0 = ks * 8;
            uint32_t bf[4][2];
            #pragma unroll
            for (int n = 0; n < 4; n++) {
                int col = cn + n * 8 + gid;
                bf[n][0] = W2u[col * W2_STRIDE + k0 + tig];
                bf[n][1] = W2u[col * W2_STRIDE + k0 + 4 + tig];
            }
            #pragma unroll
            for (int m = 0; m < 2; m++) {
                int r = rm + m * 16 + gid;
                uint32_t a0 = Hu[r * HS_STRIDE + k0 + tig];
                uint32_t a1 = Hu[(r + 8) * HS_STRIDE + k0 + tig];
                uint32_t a2 = Hu[r * HS_STRIDE + k0 + 4 + tig];
                uint32_t a3 = Hu[(r + 8) * HS_STRIDE + k0 + 4 + tig];
                #pragma unroll
                for (int n = 0; n < 4; n++)
                    mma_tf32(acc2[m][n], a0, a1, a2, a3, bf[n][0], bf[n][1]);
            }
        }
        __syncthreads();   // all H1 reads done -> safe to overwrite Hs

        // Epilogue 2: bias + relu, write H2 (fp32) back into Hs
        #pragma unroll
        for (int m = 0; m < 2; m++) {
            int r = rm + m * 16 + gid;
            #pragma unroll
            for (int n = 0; n < 4; n++) {
                int c = cn + n * 8 + 2 * tig;
                Hs[r * HS_STRIDE + c]           = fmaxf(acc2[m][n][0] + sm[OFF_B2 + c], 0.0f);
                Hs[r * HS_STRIDE + c + 1]       = fmaxf(acc2[m][n][1] + sm[OFF_B2 + c + 1], 0.0f);
                Hs[(r + 8) * HS_STRIDE + c]     = fmaxf(acc2[m][n][2] + sm[OFF_B2 + c], 0.0f);
                Hs[(r + 8) * HS_STRIDE + c + 1] = fmaxf(acc2[m][n][3] + sm[OFF_B2 + c + 1], 0.0f);
            }
        }
        __syncthreads();   // H2 ready

        // ---------------- segment-sum: in-block reduce, then global atomics --
        {
            int d    = tid & 63;          // output dim
            int part = tid >> 6;          // 4 parts x 32 rows
            int r0   = part * 32;
            float s  = 0.0f;
            int curSeg = segsm[r0];
            #pragma unroll 8
            for (int r = r0; r < r0 + 32; r++) {
                int sg = segsm[r];
                if (sg != curSeg) {
                    atomicAdd(&g_tokens[curSeg * D_H + d], s);
                    s = 0.0f; curSeg = sg;
                }
                s += Hs[r * HS_STRIDE + d];
            }
            atomicAdd(&g_tokens[curSeg * D_H + d], s);
        }
        __syncthreads();   // protect segsm/Hs before next iteration
        cur ^= 1;
    }
}

// ---------------- kernel 3: head (degenerate attention + out proj) -----------
// seq len per segment is 1 -> softmax(1x1)=1 -> ctx = tokens@Wv^T+bv
// out = ctx @ out_w^T + out_b
#define HSTR 65
#define HEAD_SMEM_FLOATS (4 * 64 * HSTR + 128)
#define HEAD_SMEM_BYTES  (HEAD_SMEM_FLOATS * 4)

__global__ void __launch_bounds__(256, 1)
head_kernel(const float* __restrict__ in_proj_w, const float* __restrict__ in_proj_b,
            const float* __restrict__ out_w, const float* __restrict__ out_b,
            float* __restrict__ out) {
    extern __shared__ float sm[];
    float* Ts = sm;
    float* Vs = Ts + 64 * HSTR;
    float* Wv = Vs + 64 * HSTR;
    float* Ow = Wv + 64 * HSTR;
    float* bv = Ow + 64 * HSTR;
    float* bo = bv + 64;
    const int tid = threadIdx.x;

    const float* wv_g = in_proj_w + 2 * 64 * 64;   // third split = Wv
    const float* bv_g = in_proj_b + 2 * 64;        // bv
    for (int i = tid; i < 4096; i += 256) {
        int r = i >> 6, c = i & 63;
        Wv[r * HSTR + c] = wv_g[i];
        Ow[r * HSTR + c] = out_w[i];
    }
    if (tid < 64) { bv[tid] = bv_g[tid]; bo[tid] = out_b[tid]; }

    int sbase = blockIdx.x * 64;
    for (int i = tid; i < 4096; i += 256) {
        int s = i >> 6, e = i & 63;
        Ts[s * HSTR + e] = g_tokens[(size_t)(sbase + s) * 64 + e];
    }
    __syncthreads();

    #pragma unroll
    for (int i = 0; i < 16; i++) {
        int e_id = tid + i * 256;
        int s = e_id >> 6, j = e_id & 63;
        float a = bv[j];
        #pragma unroll 8
        for (int e = 0; e < 64; e++) a += Ts[s * HSTR + e] * Wv[j * HSTR + e];
        Vs[s * HSTR + j] = a;
    }
    __syncthreads();

    #pragma unroll
    for (int i = 0; i < 16; i++) {
        int e_id = tid + i * 256;
        int s = e_id >> 6, d = e_id & 63;
        float a = bo[d];
        #pragma unroll 8
        for (int j = 0; j < 64; j++) a += Vs[s * HSTR + j] * Ow[d * HSTR + j];
        out[(size_t)(sbase + s) * 64 + d] = a;
    }
}

// ---------------- launch ------------------------------------------------------
extern "C" void kernel_launch(void* const* d_in, const int* in_sizes, int n_in,
                              void* d_out, int out_size) {
    const float* x      = (const float*)d_in[0];
    const int*   offset = (const int*)d_in[1];
    const float* W1     = (const float*)d_in[2];
    const float* b1     = (const float*)d_in[3];
    const float* W2     = (const float*)d_in[4];
    const float* b2     = (const float*)d_in[5];
    const float* ipw    = (const float*)d_in[6];
    const float* ipb    = (const float*)d_in[7];
    const float* ow     = (const float*)d_in[8];
    const float* ob     = (const float*)d_in[9];
    float* out = (float*)d_out;

    cudaFuncSetAttribute(mlp_seg_kernel, cudaFuncAttributeMaxDynamicSharedMemorySize,
                         SMEM_MAIN_BYTES);
    cudaFuncSetAttribute(head_kernel, cudaFuncAttributeMaxDynamicSharedMemorySize,
                         HEAD_SMEM_BYTES);

    int nsm = 148;
    cudaDeviceGetAttribute(&nsm, cudaDevAttrMultiProcessorCount, 0);

    zero_tokens_kernel<<<(N_SEGS * D_H + 255) / 256, 256>>>();
    mlp_seg_kernel<<<nsm, 256, SMEM_MAIN_BYTES>>>(x, offset, W1, b1, W2, b2);
    head_kernel<<<N_SEGS / 64, 256, HEAD_SMEM_BYTES>>>(ipw, ipb, ow, ob, out);
}

// round 5
// speedup vs baseline: 1.7157x; 1.7157x over previous
#include <cuda_runtime.h>
#include <cuda_fp16.h>
#include <cstdint>

#define N_NODES 1048576
#define N_SEGS  8192
#define TMROWS  128
#define NT      (N_NODES / TMROWS)      // 8192 tiles

// ---------------- scratch ----------------------------------------------------
__device__ float g_tokens[N_SEGS * 64];

// ---------------- smem layout (32-bit word offsets) --------------------------
// XH : X tile as fp16, [128 rows][136 f16] -> 68 words/row      = 8704 words
// HS : shared buffer: H1T [64][136 words] then Ht2 [128][68w]   = 8704 words
// W2S: W2 tf32-rounded [64][68 words]                           = 4352 words
// SEG: 128 ints
#define XH_W    0
#define HS_W    8704
#define W2S_W   17408
#define SEG_W   21760
#define SMEM_WORDS 21888
#define SMEM_BYTES (SMEM_WORDS * 4)     // 87552 B -> 2 CTAs/SM

// ---------------- helpers ----------------------------------------------------
__device__ __forceinline__ uint32_t f2tf32(float f) {
    uint32_t r;
    asm volatile("cvt.rna.tf32.f32 %0, %1;\n" : "=r"(r) : "f"(f));
    return r;
}
__device__ __forceinline__ float tf32r(float f) { return __uint_as_float(f2tf32(f)); }

__device__ __forceinline__ uint32_t h2pack(float a, float b) {
    __half2 h = __floats2half2_rn(a, b);
    return *(uint32_t*)&h;
}

__device__ __forceinline__ void mma_f16(float c[4], uint32_t a0, uint32_t a1,
                                        uint32_t a2, uint32_t a3,
                                        uint32_t b0, uint32_t b1) {
    asm volatile(
        "mma.sync.aligned.m16n8k16.row.col.f32.f16.f16.f32 "
        "{%0,%1,%2,%3}, {%4,%5,%6,%7}, {%8,%9}, {%0,%1,%2,%3};\n"
        : "+f"(c[0]), "+f"(c[1]), "+f"(c[2]), "+f"(c[3])
        : "r"(a0), "r"(a1), "r"(a2), "r"(a3), "r"(b0), "r"(b1));
}
__device__ __forceinline__ void mma_tf32(float c[4], uint32_t a0, uint32_t a1,
                                         uint32_t a2, uint32_t a3,
                                         uint32_t b0, uint32_t b1) {
    asm volatile(
        "mma.sync.aligned.m16n8k8.row.col.f32.tf32.tf32.f32 "
        "{%0,%1,%2,%3}, {%4,%5,%6,%7}, {%8,%9}, {%0,%1,%2,%3};\n"
        : "+f"(c[0]), "+f"(c[1]), "+f"(c[2]), "+f"(c[3])
        : "r"(a0), "r"(a1), "r"(a2), "r"(a3), "r"(b0), "r"(b1));
}

// ---------------- kernel 1: zero tokens --------------------------------------
__global__ void zero_tokens_kernel() {
    int i = blockIdx.x * blockDim.x + threadIdx.x;
    if (i < N_SEGS * 64) g_tokens[i] = 0.0f;
}

// ---------------- kernel 2: fused MLP + segment sum --------------------------
// GEMM1: H1T[64][128] = relu(W1[64x128] @ X^T + b1)   fp16 MMA, W1 in registers
// GEMM2: H2T[64][128] = relu(W2[64x64]  @ H1T + b2)   tf32 MMA, W2 via smem
// Warp layout (8 warps/CTA): mt = wid>>1 (j-tile of 16), ng = wid&1 (64 x-rows)
__global__ void __launch_bounds__(256, 2)
mlp_seg_kernel(const float* __restrict__ x, const int* __restrict__ offset,
               const float* __restrict__ W1, const float* __restrict__ b1,
               const float* __restrict__ W2, const float* __restrict__ b2) {
    extern __shared__ uint32_t sw[];
    uint32_t* XH  = sw + XH_W;
    uint32_t* HS  = sw + HS_W;
    uint32_t* W2S = sw + W2S_W;
    int*      SEG = (int*)(sw + SEG_W);
    float*    HSf = (float*)HS;

    const int tid = threadIdx.x;
    const int wid = tid >> 5, l = tid & 31;
    const int gid = l >> 2, tig = l & 3;
    const int mt = wid >> 1, ng = wid & 1;
    const int jm = mt * 16;
    const int nb = ng * 64;

    // ---- prologue: W1 fragments (fp16) into registers ----
    uint32_t a1r[8][4];
    {
        const float* r0 = W1 + (jm + gid) * 128;
        const float* r1 = W1 + (jm + 8 + gid) * 128;
        #pragma unroll
        for (int ks = 0; ks < 8; ks++) {
            int k = ks * 16 + 2 * tig;
            a1r[ks][0] = h2pack(r0[k], r0[k + 1]);
            a1r[ks][1] = h2pack(r1[k], r1[k + 1]);
            a1r[ks][2] = h2pack(r0[k + 8], r0[k + 9]);
            a1r[ks][3] = h2pack(r1[k + 8], r1[k + 9]);
        }
    }
    const float bias1_a = b1[jm + gid], bias1_b = b1[jm + 8 + gid];
    const float bias2_a = b2[jm + gid], bias2_b = b2[jm + 8 + gid];

    // ---- W2 (tf32-rounded) into smem, stride 68 words (68%32=4 -> no conflicts)
    for (int i = tid; i < 4096; i += 256) {
        int r = i >> 6, k = i & 63;
        ((float*)W2S)[r * 68 + k] = tf32r(W2[i]);
    }

    // ---- stage first X tile (fp32 -> fp16, stride 68 words) ----
    const int t0 = blockIdx.x;
    if (t0 < NT) {
        const float4* src = (const float4*)(x + (size_t)t0 * TMROWS * 128);
        #pragma unroll
        for (int c = 0; c < 16; c++) {
            int cid = c * 256 + tid;
            int row = cid >> 5, c4 = cid & 31;
            float4 v = src[row * 32 + c4];
            uint2 h; h.x = h2pack(v.x, v.y); h.y = h2pack(v.z, v.w);
            *(uint2*)(XH + row * 68 + c4 * 2) = h;
        }
    }
    __syncthreads();

    float acc[8][4];
    for (int t = t0; t < NT; t += gridDim.x) {
        // ---------------- GEMM1 (fp16): H1T = W1 @ X^T -----------------------
        #pragma unroll
        for (int n = 0; n < 8; n++)
            #pragma unroll
            for (int q = 0; q < 4; q++) acc[n][q] = 0.0f;

        #pragma unroll
        for (int ks = 0; ks < 8; ks++) {
            uint32_t bf[8][2];
            #pragma unroll
            for (int n = 0; n < 8; n++) {
                int xrow = nb + n * 8 + gid;
                bf[n][0] = XH[xrow * 68 + ks * 8 + tig];
                bf[n][1] = XH[xrow * 68 + ks * 8 + tig + 4];
            }
            #pragma unroll
            for (int n = 0; n < 8; n++)
                mma_f16(acc[n], a1r[ks][0], a1r[ks][1], a1r[ks][2], a1r[ks][3],
                        bf[n][0], bf[n][1]);
        }

        // ---------------- epilogue 1: bias+relu+tf32-round -> HS (H1T) -------
        #pragma unroll
        for (int n = 0; n < 8; n++) {
            int c = nb + n * 8 + 2 * tig;
            uint32_t u0 = __float_as_uint(fmaxf(acc[n][0] + bias1_a, 0.0f)) + 0x1000u;
            uint32_t u1 = __float_as_uint(fmaxf(acc[n][1] + bias1_a, 0.0f)) + 0x1000u;
            uint32_t u2 = __float_as_uint(fmaxf(acc[n][2] + bias1_b, 0.0f)) + 0x1000u;
            uint32_t u3 = __float_as_uint(fmaxf(acc[n][3] + bias1_b, 0.0f)) + 0x1000u;
            *(uint2*)(HS + (jm + gid) * 136 + c)     = make_uint2(u0, u1);
            *(uint2*)(HS + (jm + 8 + gid) * 136 + c) = make_uint2(u2, u3);
        }
        __syncthreads();   // S1: H1T ready, X consumed

        // segment ids for this tile (overlaps GEMM2)
        if (tid < TMROWS) {
            int node = t * TMROWS + tid;
            int lo = 0, hi = N_SEGS;
            #pragma unroll 1
            while (hi - lo > 1) {
                int mid = (lo + hi) >> 1;
                if (offset[mid] <= node) lo = mid; else hi = mid;
            }
            SEG[tid] = lo;
        }

        // ---------------- GEMM2 (tf32) + staging next X ----------------------
        const int tn = t + gridDim.x;
        const bool has_next = (tn < NT);
        const float4* nsrc = (const float4*)(x + (size_t)tn * TMROWS * 128);

        float acc2[8][4];
        #pragma unroll
        for (int n = 0; n < 8; n++)
            #pragma unroll
            for (int q = 0; q < 4; q++) acc2[n][q] = 0.0f;

        #pragma unroll
        for (int ks = 0; ks < 8; ks++) {
            int k0 = ks * 8;
            uint32_t a0 = W2S[(jm + gid) * 68 + k0 + tig];
            uint32_t a1 = W2S[(jm + 8 + gid) * 68 + k0 + tig];
            uint32_t a2 = W2S[(jm + gid) * 68 + k0 + tig + 4];
            uint32_t a3 = W2S[(jm + 8 + gid) * 68 + k0 + tig + 4];
            uint32_t bf[8][2];
            #pragma unroll
            for (int n = 0; n < 8; n++) {
                int xrow = nb + n * 8 + gid;
                bf[n][0] = HS[(k0 + tig) * 136 + xrow];
                bf[n][1] = HS[(k0 + tig + 4) * 136 + xrow];
            }
            #pragma unroll
            for (int n = 0; n < 8; n++)
                mma_tf32(acc2[n], a0, a1, a2, a3, bf[n][0], bf[n][1]);

            // interleave: stage 2 chunks of next tile
            if (has_next) {
                #pragma unroll
                for (int cc = 0; cc < 2; cc++) {
                    int cid = (ks * 2 + cc) * 256 + tid;
                    int row = cid >> 5, c4 = cid & 31;
                    float4 v = nsrc[row * 32 + c4];
                    uint2 h; h.x = h2pack(v.x, v.y); h.y = h2pack(v.z, v.w);
                    *(uint2*)(XH + row * 68 + c4 * 2) = h;
                }
            }
        }
        __syncthreads();   // S2: all H1T reads done

        // ---------------- epilogue 2: bias+relu -> HS (Ht2 [xrow][j], s=68) --
        #pragma unroll
        for (int n = 0; n < 8; n++) {
            int xr = nb + n * 8 + 2 * tig;
            HSf[xr * 68 + jm + gid]           = fmaxf(acc2[n][0] + bias2_a, 0.0f);
            HSf[(xr + 1) * 68 + jm + gid]     = fmaxf(acc2[n][1] + bias2_a, 0.0f);
            HSf[xr * 68 + jm + 8 + gid]       = fmaxf(acc2[n][2] + bias2_b, 0.0f);
            HSf[(xr + 1) * 68 + jm + 8 + gid] = fmaxf(acc2[n][3] + bias2_b, 0.0f);
        }
        __syncthreads();   // S3: Ht2 + SEG ready

        // ---------------- segment reduce + global atomics --------------------
        {
            int d = tid & 63, part = tid >> 6, r0 = part * 32;
            float s = 0.0f;
            int cs = SEG[r0];
            #pragma unroll 8
            for (int r = r0; r < r0 + 32; r++) {
                int sg = SEG[r];
                if (sg != cs) { atomicAdd(&g_tokens[cs * 64 + d], s); s = 0.0f; cs = sg; }
                s += HSf[r * 68 + d];
            }
            atomicAdd(&g_tokens[cs * 64 + d], s);
        }
        __syncthreads();   // S4: HS/SEG free for next iteration
    }
}

// ---------------- kernel 3: head (degenerate attention + out proj) -----------
// seq len per segment is 1 -> softmax(1x1)=1 -> ctx = tokens@Wv^T+bv
#define HSTR 65
#define HEAD_SMEM_BYTES ((4 * 64 * HSTR + 128) * 4)

__global__ void __launch_bounds__(256, 1)
head_kernel(const float* __restrict__ in_proj_w, const float* __restrict__ in_proj_b,
            const float* __restrict__ out_w, const float* __restrict__ out_b,
            float* __restrict__ out) {
    extern __shared__ float sm[];
    float* Ts = sm;
    float* Vs = Ts + 64 * HSTR;
    float* Wv = Vs + 64 * HSTR;
    float* Ow = Wv + 64 * HSTR;
    float* bv = Ow + 64 * HSTR;
    float* bo = bv + 64;
    const int tid = threadIdx.x;

    const float* wv_g = in_proj_w + 2 * 64 * 64;
    const float* bv_g = in_proj_b + 2 * 64;
    for (int i = tid; i < 4096; i += 256) {
        int r = i >> 6, c = i & 63;
        Wv[r * HSTR + c] = wv_g[i];
        Ow[r * HSTR + c] = out_w[i];
    }
    if (tid < 64) { bv[tid] = bv_g[tid]; bo[tid] = out_b[tid]; }

    int sbase = blockIdx.x * 64;
    for (int i = tid; i < 4096; i += 256) {
        int s = i >> 6, e = i & 63;
        Ts[s * HSTR + e] = g_tokens[(size_t)(sbase + s) * 64 + e];
    }
    __syncthreads();

    #pragma unroll
    for (int i = 0; i < 16; i++) {
        int e_id = tid + i * 256;
        int s = e_id >> 6, j = e_id & 63;
        float a = bv[j];
        #pragma unroll 8
        for (int e = 0; e < 64; e++) a += Ts[s * HSTR + e] * Wv[j * HSTR + e];
        Vs[s * HSTR + j] = a;
    }
    __syncthreads();

    #pragma unroll
    for (int i = 0; i < 16; i++) {
        int e_id = tid + i * 256;
        int s = e_id >> 6, d = e_id & 63;
        float a = bo[d];
        #pragma unroll 8
        for (int j = 0; j < 64; j++) a += Vs[s * HSTR + j] * Ow[d * HSTR + j];
        out[(size_t)(sbase + s) * 64 + d] = a;
    }
}

// ---------------- launch ------------------------------------------------------
extern "C" void kernel_launch(void* const* d_in, const int* in_sizes, int n_in,
                              void* d_out, int out_size) {
    const float* x      = (const float*)d_in[0];
    const int*   offset = (const int*)d_in[1];
    const float* W1     = (const float*)d_in[2];
    const float* b1     = (const float*)d_in[3];
    const float* W2     = (const float*)d_in[4];
    const float* b2     = (const float*)d_in[5];
    const float* ipw    = (const float*)d_in[6];
    const float* ipb    = (const float*)d_in[7];
    const float* ow     = (const float*)d_in[8];
    const float* ob     = (const float*)d_in[9];
    float* out = (float*)d_out;

    cudaFuncSetAttribute(mlp_seg_kernel, cudaFuncAttributeMaxDynamicSharedMemorySize,
                         SMEM_BYTES);
    cudaFuncSetAttribute(head_kernel, cudaFuncAttributeMaxDynamicSharedMemorySize,
                         HEAD_SMEM_BYTES);

    int nsm = 148;
    cudaDeviceGetAttribute(&nsm, cudaDevAttrMultiProcessorCount, 0);

    zero_tokens_kernel<<<(N_SEGS * 64 + 255) / 256, 256>>>();
    mlp_seg_kernel<<<2 * nsm, 256, SMEM_BYTES>>>(x, offset, W1, b1, W2, b2);
    head_kernel<<<N_SEGS / 64, 256, HEAD_SMEM_BYTES>>>(ipw, ipb, ow, ob, out);
}